// round 14
// baseline (speedup 1.0000x reference)
#include <cuda_runtime.h>
#include <cuda_fp16.h>
#include <math.h>
#include <stdint.h>

// ---------------- problem constants ----------------
#define BB 8
#define LL 4096
#define DD 512
#define TOPK 8
#define NFFT 4096
static const size_t BLD = (size_t)BB * LL * DD;   // 16,777,216

// ---------------- device scratch ----------------
__device__ __half g_xsf[(size_t)BB * LL * DD];      // fp16 x_s
__device__ __half g_xwf[(size_t)BB * LL * DD];      // fp16 x_w
__device__ __half g_P  [(size_t)BB * LL * DD];      // x_s @ (Wo Wv)^T, fp16
__device__ __half g_qTh[(size_t)BB * DD * LL];      // q transposed [B,D,L] fp16
__device__ __half g_kTh[(size_t)BB * DD * LL];
__device__ __half g_wqf[DD * DD];
__device__ __half g_wkf[DD * DD];
__device__ __half g_wcb[DD * DD];          // fp16(Wo @ Wv)
__device__ __half g_wc [DD * 1536];        // conv weights relaid [n][kk*512+i]
__device__ float g_bcomb[DD];              // Wo @ bv + bo
__device__ float2 g_S[BB * 2049];          // Hermitian half-spectrum per batch
__device__ float2 g_tw[NFFT / 2];
__device__ float g_w[BB * TOPK];
__device__ int   g_delay[BB * TOPK];
__device__ int   g_cnt[BB];                // fft completion counters per batch

// ---------------- helpers ----------------
__device__ __forceinline__ uint32_t smem_u32(const void* p) {
    uint32_t a;
    asm("{ .reg .u64 t; cvta.to.shared.u64 t, %1; cvt.u32.u64 %0, t; }" : "=r"(a) : "l"(p));
    return a;
}

__device__ __forceinline__ void ldmx4(uint32_t* r, uint32_t addr) {
    asm volatile("ldmatrix.sync.aligned.m8n8.x4.shared.b16 {%0,%1,%2,%3}, [%4];"
                 : "=r"(r[0]), "=r"(r[1]), "=r"(r[2]), "=r"(r[3]) : "r"(addr));
}

__device__ __forceinline__ void mma_f16(float* d, const uint32_t* a, uint32_t b0, uint32_t b1) {
    asm volatile(
        "mma.sync.aligned.m16n8k16.row.col.f32.f16.f16.f32 "
        "{%0,%1,%2,%3}, {%4,%5,%6,%7}, {%8,%9}, {%0,%1,%2,%3};"
        : "+f"(d[0]), "+f"(d[1]), "+f"(d[2]), "+f"(d[3])
        : "r"(a[0]), "r"(a[1]), "r"(a[2]), "r"(a[3]), "r"(b0), "r"(b1));
}

#define CP_ASYNC16(dst, src) \
    asm volatile("cp.async.cg.shared.global [%0], [%1], 16;" :: "r"(dst), "l"(src))
#define CP_COMMIT() asm volatile("cp.async.commit_group;")
#define CP_WAIT1()  asm volatile("cp.async.wait_group 1;")
#define CP_WAIT0()  asm volatile("cp.async.wait_group 0;")

__device__ __forceinline__ uint32_t sw64(uint32_t off) {
    return off ^ ((off >> 3) & 0x30);
}

// ---------------- merged setup + split ----------------
__device__ __forceinline__ void cvt_one4(const float4* __restrict__ x,
                                         __half2* __restrict__ f, int i) {
    float4 v = x[i];
    f[2 * i]     = __floats2half2_rn(v.x, v.y);
    f[2 * i + 1] = __floats2half2_rn(v.z, v.w);
}

__global__ void prep_kernel(const float4* __restrict__ xs,
                            const float4* __restrict__ xw,
                            const float4* __restrict__ Wq,
                            const float4* __restrict__ Wk,
                            const float* __restrict__ Wconv,
                            const float* __restrict__ Wo,
                            const float* __restrict__ Wv,
                            const float* __restrict__ bv,
                            const float* __restrict__ bo) {
    int bid = blockIdx.x;
    int tid = threadIdx.x;
    if (bid < 4096) {
        int base = bid * 1024 + tid;
#pragma unroll
        for (int j = 0; j < 4; ++j) cvt_one4(xs, (__half2*)g_xsf, base + j * 256);
        return;
    } else if (bid < 8192) {
        int base = (bid - 4096) * 1024 + tid;
#pragma unroll
        for (int j = 0; j < 4; ++j) cvt_one4(xw, (__half2*)g_xwf, base + j * 256);
        return;
    } else if (bid < 8448) {
        cvt_one4(Wq, (__half2*)g_wqf, (bid - 8192) * 256 + tid);
        return;
    } else if (bid < 8704) {
        cvt_one4(Wk, (__half2*)g_wkf, (bid - 8448) * 256 + tid);
        return;
    } else if (bid < 11776) {
        int idx = (bid - 8704) * 256 + tid;         // conv relay; over 512*1536
        int n = idx / 1536;
        int r = idx - n * 1536;
        int kk = r >> 9;
        int i = r & 511;
        g_wc[idx] = __float2half_rn(Wconv[((size_t)n * 512 + i) * 3 + kk]);
        return;
    }
    int blk = bid - 11776;                           // 0..385
    if (blk < 256) {
        __shared__ float As[32][33], Bs[32][33];
        int bi = (blk >> 4) * 32, bj = (blk & 15) * 32;
        int tx = tid & 15, ty = tid >> 4;
        float a00 = 0.f, a01 = 0.f, a10 = 0.f, a11 = 0.f;
        for (int m0 = 0; m0 < 512; m0 += 32) {
            for (int r = ty; r < 32; r += 16) {
                As[r][tx]      = Wo[(bi + r) * 512 + m0 + tx];
                As[r][tx + 16] = Wo[(bi + r) * 512 + m0 + tx + 16];
                Bs[r][tx]      = Wv[(m0 + r) * 512 + bj + tx];
                Bs[r][tx + 16] = Wv[(m0 + r) * 512 + bj + tx + 16];
            }
            __syncthreads();
#pragma unroll
            for (int m = 0; m < 32; ++m) {
                float x0 = As[ty][m], x1 = As[ty + 16][m];
                float y0 = Bs[m][tx], y1 = Bs[m][tx + 16];
                a00 += x0 * y0; a01 += x0 * y1; a10 += x1 * y0; a11 += x1 * y1;
            }
            __syncthreads();
        }
        int i00 = (bi + ty) * 512 + bj + tx;
        int i10 = (bi + ty + 16) * 512 + bj + tx;
        g_wcb[i00] = __float2half_rn(a00);      g_wcb[i00 + 16] = __float2half_rn(a01);
        g_wcb[i10] = __float2half_rn(a10);      g_wcb[i10 + 16] = __float2half_rn(a11);
    } else if (blk < 320) {
        int o = (blk - 256) * 8 + (tid >> 5);
        int lane = tid & 31;
        float s = 0.f;
        for (int m = lane; m < 512; m += 32) s += Wo[o * 512 + m] * bv[m];
#pragma unroll
        for (int off = 16; off; off >>= 1) s += __shfl_xor_sync(0xFFFFFFFFu, s, off);
        if (lane == 0) g_bcomb[o] = s + bo[o];
    } else if (blk == 320) {
        for (int j = tid; j < 2048; j += 256) {
            float s, c;
            sincospif(-2.0f * (float)j / (float)NFFT, &s, &c);
            g_tw[j] = make_float2(c, s);
        }
    } else {
        int i = (blk - 321) * 256 + tid;
        if (i < BB * 2049) g_S[i] = make_float2(0.f, 0.f);
        if (blk == 321 && tid < BB) g_cnt[tid] = 0;
    }
}

// ---------------- shared fp16 GEMM mainloop (3-stage ring, lookahead-2, 1 barrier/iter) ----------------
__device__ __forceinline__ void load_chunk16(
    int ch, int stage, int rowA, int rowB, bool conv, int m0, int n0, int tid, uint32_t sbase,
    const char* __restrict__ A, const char* __restrict__ B)
{
    uint32_t st = sbase + stage * 16384;
    int r = tid >> 1;
    int seg0 = (tid & 1) << 1;

    size_t abyte;
    if (conv) {
        int k0e = ch << 5;                 // element offset in logical K=1536 (fp16)
        int m = m0 + r;
        int kk = k0e >> 9;
        int ii = k0e & 511;
        int bb = m >> 12;
        int tt = ((m & 4095) + kk + 4095) & 4095;   // t + kk - 1 mod L
        abyte = ((((size_t)(bb << 12) + tt) << 9) + ii) * 2;
    } else {
        abyte = (size_t)(m0 + r) * rowA + (ch << 6);
    }
    size_t bbyte = (size_t)(n0 + r) * rowB + (ch << 6);

#pragma unroll
    for (int s2 = 0; s2 < 2; ++s2) {
        int seg = seg0 + s2;
        uint32_t soff = sw64((r << 6) + (seg << 4));
        CP_ASYNC16(st + soff, A + abyte + (seg << 4));
        CP_ASYNC16(st + 8192 + soff, B + bbyte + (seg << 4));
    }
    CP_COMMIT();
}

__device__ __forceinline__ void gemm_mainloop(
    float acc[4][4][4], const char* __restrict__ A, const char* __restrict__ B,
    int rowA, int rowB, int T, bool conv, int m0, int n0, int tid, uint32_t sbase)
{
    const int wid = tid >> 5;
    const int lane = tid & 31;
    const int wm = wid >> 2;
    const int wn = wid & 3;
    const int lrow = lane & 15;
    const int lseg = lane >> 4;

#pragma unroll
    for (int i = 0; i < 4; ++i)
#pragma unroll
        for (int j = 0; j < 4; ++j)
#pragma unroll
            for (int r = 0; r < 4; ++r) acc[i][j][r] = 0.f;

    // lookahead-2 over a 3-stage ring: the load issued at iter 'it' targets stage
    // (it+2)%3 == (it-1)%3, whose reads were fenced by THIS iter's top barrier.
    load_chunk16(0, 0, rowA, rowB, conv, m0, n0, tid, sbase, A, B);
    load_chunk16(1, 1, rowA, rowB, conv, m0, n0, tid, sbase, A, B);

    int s = 0;
    for (int it = 0; it < T; ++it) {
        if (it + 1 < T) { CP_WAIT1(); } else { CP_WAIT0(); }
        __syncthreads();

        uint32_t st = sbase + s * 16384;
#pragma unroll
        for (int ks = 0; ks < 2; ++ks) {
            int cseg = (ks << 1) + lseg;
            uint32_t a[4][4], b2[2][4];
#pragma unroll
            for (int mt = 0; mt < 4; ++mt) {
                int row = (wm << 6) + (mt << 4) + lrow;
                ldmx4(a[mt], st + sw64((row << 6) + (cseg << 4)));
            }
#pragma unroll
            for (int bt = 0; bt < 2; ++bt) {
                int row = (wn << 5) + (bt << 4) + lrow;
                ldmx4(b2[bt], st + 8192 + sw64((row << 6) + (cseg << 4)));
            }
#pragma unroll
            for (int mt = 0; mt < 4; ++mt)
#pragma unroll
                for (int nt = 0; nt < 4; ++nt)
                    mma_f16(acc[mt][nt], a[mt],
                            b2[nt >> 1][nt & 1], b2[nt >> 1][(nt & 1) + 2]);
        }
        if (it + 2 < T) {
            int s2 = (s == 0) ? 2 : s - 1;     // (it+2)%3
            load_chunk16(it + 2, s2, rowA, rowB, conv, m0, n0, tid, sbase, A, B);
        }
        s = (s == 2) ? 0 : s + 1;
    }
    __syncthreads();    // protect smem reuse by epilogues
}

// ---------------- q/k GEMM (fp16, transposed fp16 output) ----------------
__global__ void __launch_bounds__(256, 2) qk_gemm(
    const float* __restrict__ bq, const float* __restrict__ bk)
{
    extern __shared__ char smraw[];
    uint32_t sbase = (smem_u32(smraw) + 1023u) & ~1023u;

    const int mode = blockIdx.x >> 10;     // 0 = q (x_w @ Wq), 1 = k (x_s @ Wk)
    const int rr = blockIdx.x & 1023;
    const int m0 = (rr >> 2) << 7;
    const int n0 = (rr & 3) << 7;
    const int tid = threadIdx.x;
    const int wid = tid >> 5;
    const int lane = tid & 31;
    const int wm = wid >> 2;
    const int wn = wid & 3;

    const char* A = (const char*)(mode ? g_xsf : g_xwf);
    const char* B = (const char*)(mode ? g_wkf : g_wqf);

    float acc[4][4][4];
    gemm_mainloop(acc, A, B, 1024, 1024, 16, false, m0, n0, tid, sbase);

    // fp16 transposed epilogue via smem into [B, D, L]
    const int er = lane >> 2;
    const int ec = (lane & 3) << 1;
    __half* sth = (__half*)smraw;
    const float* bias = mode ? bk : bq;
    __half* Cout = mode ? g_kTh : g_qTh;
#pragma unroll
    for (int mt = 0; mt < 4; ++mt)
#pragma unroll
        for (int nt = 0; nt < 4; ++nt) {
            int r0 = (wm << 6) + (mt << 4) + er;
            int c0 = (wn << 5) + (nt << 3) + ec;
            float b0v = bias[n0 + c0], b1v = bias[n0 + c0 + 1];
            sth[c0 * 136 + r0]            = __float2half_rn(acc[mt][nt][0] + b0v);
            sth[(c0 + 1) * 136 + r0]      = __float2half_rn(acc[mt][nt][1] + b1v);
            sth[c0 * 136 + r0 + 8]        = __float2half_rn(acc[mt][nt][2] + b0v);
            sth[(c0 + 1) * 136 + r0 + 8]  = __float2half_rn(acc[mt][nt][3] + b1v);
        }
    __syncthreads();
    int bb = m0 >> 12, l0 = m0 & 4095;
#pragma unroll
    for (int i = 0; i < 8; ++i) {
        int idx = tid + (i << 8);
        int c = idx >> 4;
        int g8 = (idx & 15) << 3;
        uint4 v = *(uint4*)&sth[c * 136 + g8];
        *(uint4*)&Cout[(((size_t)(bb << 9) + n0 + c) << 12) + l0 + g8] = v;
    }
}

// ---------------- fused radix-8 FFT (4 passes) ----------------
__device__ __forceinline__ float2 cmulf(float2 w, float2 z) {
    return make_float2(w.x * z.x - w.y * z.y, w.x * z.y + w.y * z.x);
}
__device__ __forceinline__ float2 mni(float2 u) { return make_float2(u.y, -u.x); }
__device__ __forceinline__ float2 rot45(float2 u) {
    const float r = 0.70710678118654752f;
    return make_float2(r * (u.x + u.y), r * (u.y - u.x));
}
__device__ __forceinline__ float2 cadd(float2 a, float2 b) { return make_float2(a.x + b.x, a.y + b.y); }
__device__ __forceinline__ float2 csub(float2 a, float2 b) { return make_float2(a.x - b.x, a.y - b.y); }

__device__ __forceinline__ void fft_stages_r8(float2* zs, const float2* tw, int tid) {
#pragma unroll
    for (int p = 0; p < 4; ++p) {
        const int h = 1 << (3 * p);
#pragma unroll
        for (int jj = 0; jj < 2; ++jj) {
            int j = tid + (jj << 8);
            int pos = j & (h - 1);
            int grp = j >> (3 * p);
            int base = (grp << (3 * p + 3)) + pos;
            float2 x0 = zs[base],         x1 = zs[base + h];
            float2 x2 = zs[base + 2 * h], x3 = zs[base + 3 * h];
            float2 x4 = zs[base + 4 * h], x5 = zs[base + 5 * h];
            float2 x6 = zs[base + 6 * h], x7 = zs[base + 7 * h];
            float2 wA = tw[pos << (11 - 3 * p)];
            float2 wB = tw[pos << (10 - 3 * p)];
            float2 wC = tw[pos << (9 - 3 * p)];
            float2 t;
            t = cmulf(wA, x1); float2 a0 = cadd(x0, t), a1 = csub(x0, t);
            t = cmulf(wA, x3); float2 a2 = cadd(x2, t), a3 = csub(x2, t);
            t = cmulf(wA, x5); float2 a4 = cadd(x4, t), a5 = csub(x4, t);
            t = cmulf(wA, x7); float2 a6 = cadd(x6, t), a7 = csub(x6, t);
            t = cmulf(wB, a2);      float2 b0 = cadd(a0, t), b2 = csub(a0, t);
            t = mni(cmulf(wB, a3)); float2 b1 = cadd(a1, t), b3 = csub(a1, t);
            t = cmulf(wB, a6);      float2 b4 = cadd(a4, t), b6 = csub(a4, t);
            t = mni(cmulf(wB, a7)); float2 b5 = cadd(a5, t), b7 = csub(a5, t);
            t = cmulf(wC, b4);             zs[base]         = cadd(b0, t); zs[base + 4 * h] = csub(b0, t);
            t = rot45(cmulf(wC, b5));      zs[base + h]     = cadd(b1, t); zs[base + 5 * h] = csub(b1, t);
            t = mni(cmulf(wC, b6));        zs[base + 2 * h] = cadd(b2, t); zs[base + 6 * h] = csub(b2, t);
            t = mni(rot45(cmulf(wC, b7))); zs[base + 3 * h] = cadd(b3, t); zs[base + 7 * h] = csub(b3, t);
        }
        __syncthreads();
    }
}

// ---------------- combo: fft_cross (512 CTAs, interleaved) + conv/P GEMM (2048 CTAs) ----------------
__global__ void __launch_bounds__(256, 2) combo_kernel(float* __restrict__ out_w)
{
    extern __shared__ char smraw[];
    const int bid = blockIdx.x;
    const int tid = threadIdx.x;

    if (bid < 2048 && (bid & 3) == 3) {
        // ---------------- fft_cross part ----------------
        float2* sm = (float2*)smraw;
        float2* zs  = sm;            // 4096
        float2* tw  = sm + 4096;     // 2048
        float2* acc = sm + 6144;     // 2049

        const int fidx = bid >> 2;
        const int b = fidx >> 6;
        const int dg = (fidx & 63) << 3;

        for (int j = tid; j < 2048; j += 256) tw[j] = g_tw[j];
        for (int f = tid; f <= 2048; f += 256) acc[f] = make_float2(0.f, 0.f);

        for (int c = 0; c < 8; ++c) {
            int d = dg + c;
            const __half2* qrow = (const __half2*)(g_qTh + (((size_t)b * DD + d) << 12));
            const __half2* krow = (const __half2*)(g_kTh + (((size_t)b * DD + d) << 12));
            __syncthreads();
#pragma unroll
            for (int k = 0; k < 8; ++k) {
                int idx = tid + (k << 8);
                float2 q2 = __half22float2(qrow[idx]);
                float2 k2 = __half22float2(krow[idx]);
                int t0 = idx << 1;
                zs[(int)(__brev((unsigned)t0) >> 20)]       = make_float2(q2.x, k2.x);
                zs[(int)(__brev((unsigned)(t0 + 1)) >> 20)] = make_float2(q2.y, k2.y);
            }
            __syncthreads();
            fft_stages_r8(zs, tw, tid);
            for (int f = tid; f <= 2048; f += 256) {
                float2 Zf = zs[f];
                float2 Zc = zs[(4096 - f) & 4095];
                float Qr = 0.5f * (Zf.x + Zc.x);
                float Qi = 0.5f * (Zf.y - Zc.y);
                float Kr = 0.5f * (Zf.y + Zc.y);
                float Ki = 0.5f * (Zc.x - Zf.x);
                float2 a2 = acc[f];
                a2.x += Qr * Kr + Qi * Ki;
                a2.y += Qi * Kr - Qr * Ki;
                acc[f] = a2;
            }
        }
        __syncthreads();
        for (int f = tid; f <= 2048; f += 256) {
            atomicAdd(&g_S[b * 2049 + f].x, acc[f].x);
            atomicAdd(&g_S[b * 2049 + f].y, acc[f].y);
        }

        // last-block: inline IFFT + top-k for this batch
        __shared__ int s_flag;
        __syncthreads();
        if (tid == 0) {
            __threadfence();
            int old = atomicAdd(&g_cnt[b], 1);
            s_flag = (old == 63) ? 1 : 0;
        }
        __syncthreads();
        if (!s_flag) return;
        __threadfence();

        float* mv = (float*)(sm + 6144);   // reuse acc region (4096 floats)

        for (int f = tid; f < 4096; f += 256) {
            float2 sv;
            if (f <= 2048) {
                sv = g_S[b * 2049 + f];
                sv.y = -sv.y;              // conj -> IFFT via forward FFT
            } else {
                sv = g_S[b * 2049 + (4096 - f)];
            }
            zs[(int)(__brev((unsigned)f) >> 20)] = sv;
        }
        __syncthreads();
        fft_stages_r8(zs, tw, tid);

        const float scale = 1.0f / (4096.0f * 512.0f);
        for (int n = tid; n < 4096; n += 256) mv[n] = zs[n].x * scale;
        __syncthreads();

        __shared__ float red_v[256];
        __shared__ int   red_i[256];
        __shared__ float s_tv[TOPK];
        __shared__ int   s_ti[TOPK];

        for (int it = 0; it < TOPK; ++it) {
            float bv = -3.402823e38f; int bi = 1 << 30;
            for (int n = tid; n < 4096; n += 256) {
                float v = mv[n];
                if (v > bv || (v == bv && n < bi)) { bv = v; bi = n; }
            }
            red_v[tid] = bv; red_i[tid] = bi;
            __syncthreads();
            for (int s = 128; s > 0; s >>= 1) {
                if (tid < s) {
                    float v2 = red_v[tid + s]; int i2 = red_i[tid + s];
                    if (v2 > red_v[tid] || (v2 == red_v[tid] && i2 < red_i[tid])) {
                        red_v[tid] = v2; red_i[tid] = i2;
                    }
                }
                __syncthreads();
            }
            if (tid == 0) {
                s_tv[it] = red_v[0]; s_ti[it] = red_i[0];
                mv[red_i[0]] = -3.402823e38f;
            }
            __syncthreads();
        }

        if (tid == 0) {
            float mx = s_tv[0];
            float ex[TOPK]; float sum = 0.f;
            for (int i = 0; i < TOPK; ++i) { ex[i] = expf(s_tv[i] - mx); sum += ex[i]; }
            for (int i = 0; i < TOPK; ++i) {
                g_w[b * TOPK + i] = ex[i] / sum;
                g_delay[b * TOPK + i] = s_ti[i];
            }
        }
        return;
    }

    // ---------------- GEMM part: conv (gidx < 1024) or P ----------------
    uint32_t sbase = (smem_u32(smraw) + 1023u) & ~1023u;
    int gidx = (bid < 2048) ? (bid - (bid >> 2)) : (1536 + (bid - 2048));
    const bool is_conv = (gidx < 1024);
    const int rr = gidx & 1023;
    const int m0 = (rr >> 2) << 7;
    const int n0 = (rr & 3) << 7;
    const int wid = tid >> 5;
    const int lane = tid & 31;
    const int wm = wid >> 2;
    const int wn = wid & 3;

    float acc[4][4][4];
    if (is_conv) {
        gemm_mainloop(acc, (const char*)g_xwf, (const char*)g_wc, 1024, 3072, 48, true,
                      m0, n0, tid, sbase);
    } else {
        gemm_mainloop(acc, (const char*)g_xsf, (const char*)g_wcb, 1024, 1024, 16, false,
                      m0, n0, tid, sbase);
    }

    const int er = lane >> 2;
    const int ec = (lane & 3) << 1;
    if (is_conv) {
#pragma unroll
        for (int mt = 0; mt < 4; ++mt)
#pragma unroll
            for (int nt = 0; nt < 4; ++nt) {
                int r0 = m0 + (wm << 6) + (mt << 4) + er;
                int c0 = n0 + (wn << 5) + (nt << 3) + ec;
                size_t o0 = ((size_t)r0 << 9) + c0;
                size_t o1 = ((size_t)(r0 + 8) << 9) + c0;
                *(float2*)&out_w[o0] = make_float2(acc[mt][nt][0], acc[mt][nt][1]);
                *(float2*)&out_w[o1] = make_float2(acc[mt][nt][2], acc[mt][nt][3]);
            }
    } else {
#pragma unroll
        for (int mt = 0; mt < 4; ++mt)
#pragma unroll
            for (int nt = 0; nt < 4; ++nt) {
                int r0 = m0 + (wm << 6) + (mt << 4) + er;
                int c0 = n0 + (wn << 5) + (nt << 3) + ec;
                *(__half2*)&g_P[((size_t)r0 << 9) + c0] =
                    __floats2half2_rn(acc[mt][nt][0], acc[mt][nt][1]);
                *(__half2*)&g_P[((size_t)(r0 + 8) << 9) + c0] =
                    __floats2half2_rn(acc[mt][nt][2], acc[mt][nt][3]);
            }
    }
}

// ---------------- final aggregation: out_s = x_s + sum_i w_i * roll(P, d_i) + bcomb ----------------
__global__ void final_agg(const float* __restrict__ xs, float* __restrict__ out) {
    size_t idx = (size_t)blockIdx.x * 256 + threadIdx.x;   // over B*L rows x 64 uint4-groups
    int c = (int)(idx & 63);
    size_t row = idx >> 6;
    int b = (int)(row >> 12);
    int t = (int)(row & 4095);

    float wloc[TOPK]; int dloc[TOPK];
#pragma unroll
    for (int i = 0; i < TOPK; ++i) { wloc[i] = g_w[b * TOPK + i]; dloc[i] = g_delay[b * TOPK + i]; }

    float acc[8];
    {
        const float4 b0 = *(const float4*)&g_bcomb[c << 3];
        const float4 b1 = *(const float4*)&g_bcomb[(c << 3) + 4];
        acc[0] = b0.x; acc[1] = b0.y; acc[2] = b0.z; acc[3] = b0.w;
        acc[4] = b1.x; acc[5] = b1.y; acc[6] = b1.z; acc[7] = b1.w;
    }
#pragma unroll
    for (int i = 0; i < TOPK; ++i) {
        int ts = (t + dloc[i]) & 4095;
        const uint4 raw = *(const uint4*)(g_P + (((size_t)(b << 12) + ts) << 9) + (c << 3));
        const __half2* p = (const __half2*)&raw;
        float w = wloc[i];
#pragma unroll
        for (int j = 0; j < 4; ++j) {
            float2 f = __half22float2(p[j]);
            acc[2 * j]     += w * f.x;
            acc[2 * j + 1] += w * f.y;
        }
    }
    size_t o = (row << 9) + (c << 3);
    const float4 xv0 = *(const float4*)&xs[o];
    const float4 xv1 = *(const float4*)&xs[o + 4];
    float4 r0 = make_float4(acc[0] + xv0.x, acc[1] + xv0.y, acc[2] + xv0.z, acc[3] + xv0.w);
    float4 r1 = make_float4(acc[4] + xv1.x, acc[5] + xv1.y, acc[6] + xv1.z, acc[7] + xv1.w);
    *(float4*)&out[o]     = r0;
    *(float4*)&out[o + 4] = r1;
}

// ---------------- host launch ----------------
extern "C" void kernel_launch(void* const* d_in, const int* in_sizes, int n_in,
                              void* d_out, int out_size) {
    const float* x_s   = (const float*)d_in[0];
    const float* x_w   = (const float*)d_in[1];
    const float* Wq    = (const float*)d_in[2];
    const float* bq    = (const float*)d_in[3];
    const float* Wk    = (const float*)d_in[4];
    const float* bk    = (const float*)d_in[5];
    const float* Wv    = (const float*)d_in[6];
    const float* bv    = (const float*)d_in[7];
    const float* Wo    = (const float*)d_in[8];
    const float* bo    = (const float*)d_in[9];
    const float* Wconv = (const float*)d_in[10];

    float* out_s = (float*)d_out;
    float* out_w = out_s + BLD;

    const int SMEM_GEMM = 3 * 16384 + 1024;      // 50176
    const int SMEM_COMBO = 66560;                // fft path needs (4096+2048+2049)*8
    cudaFuncSetAttribute(qk_gemm, cudaFuncAttributeMaxDynamicSharedMemorySize, SMEM_GEMM);
    cudaFuncSetAttribute(combo_kernel, cudaFuncAttributeMaxDynamicSharedMemorySize, SMEM_COMBO);

    // 1: conversions + conv relay + twiddles + spectrum zero + Wcomb + bcomb (merged)
    prep_kernel<<<12162, 256>>>((const float4*)x_s, (const float4*)x_w,
                                (const float4*)Wq, (const float4*)Wk, Wconv,
                                Wo, Wv, bv, bo);
    // 2: q and k projections (transposed fp16 outputs)
    qk_gemm<<<2048, 256, SMEM_GEMM>>>(bq, bk);
    // 3: fft_cross interleaved with conv + P GEMMs; last fft CTA per batch does IFFT+top-k
    combo_kernel<<<2560, 256, SMEM_COMBO>>>(out_w);
    // 4: out_s = x_s + sum_i w_i * roll(P, d_i) + bcomb
    final_agg<<<8192, 256>>>(x_s, out_s);
}

// round 15
// speedup vs baseline: 1.0399x; 1.0399x over previous
#include <cuda_runtime.h>
#include <cuda_fp16.h>
#include <math.h>
#include <stdint.h>

// ---------------- problem constants ----------------
#define BB 8
#define LL 4096
#define DD 512
#define TOPK 8
#define NFFT 4096
static const size_t BLD = (size_t)BB * LL * DD;   // 16,777,216

// ---------------- device scratch ----------------
__device__ __half g_xsf[(size_t)BB * LL * DD];      // fp16 x_s
__device__ __half g_xwf[(size_t)BB * LL * DD];      // fp16 x_w
__device__ __half g_P  [(size_t)BB * LL * DD];      // x_s @ (Wo Wv)^T, fp16
__device__ __half g_qTh[(size_t)BB * DD * LL];      // q transposed [B,D,L] fp16
__device__ __half g_kTh[(size_t)BB * DD * LL];
__device__ __half g_wqf[DD * DD];
__device__ __half g_wkf[DD * DD];
__device__ __half g_wcb[DD * DD];          // fp16(Wo @ Wv)
__device__ __half g_wc [DD * 1536];        // conv weights relaid [n][kk*512+i]
__device__ float g_bcomb[DD];              // Wo @ bv + bo
__device__ float2 g_S[BB * 2049];          // Hermitian half-spectrum per batch
__device__ float2 g_tw[NFFT / 2];
__device__ float g_w[BB * TOPK];
__device__ int   g_delay[BB * TOPK];
__device__ int   g_cnt[BB];                // fft completion counters per batch

// ---------------- helpers ----------------
__device__ __forceinline__ uint32_t smem_u32(const void* p) {
    uint32_t a;
    asm("{ .reg .u64 t; cvta.to.shared.u64 t, %1; cvt.u32.u64 %0, t; }" : "=r"(a) : "l"(p));
    return a;
}

__device__ __forceinline__ void ldmx4(uint32_t* r, uint32_t addr) {
    asm volatile("ldmatrix.sync.aligned.m8n8.x4.shared.b16 {%0,%1,%2,%3}, [%4];"
                 : "=r"(r[0]), "=r"(r[1]), "=r"(r[2]), "=r"(r[3]) : "r"(addr));
}

__device__ __forceinline__ void mma_f16(float* d, const uint32_t* a, uint32_t b0, uint32_t b1) {
    asm volatile(
        "mma.sync.aligned.m16n8k16.row.col.f32.f16.f16.f32 "
        "{%0,%1,%2,%3}, {%4,%5,%6,%7}, {%8,%9}, {%0,%1,%2,%3};"
        : "+f"(d[0]), "+f"(d[1]), "+f"(d[2]), "+f"(d[3])
        : "r"(a[0]), "r"(a[1]), "r"(a[2]), "r"(a[3]), "r"(b0), "r"(b1));
}

#define CP_ASYNC16(dst, src) \
    asm volatile("cp.async.cg.shared.global [%0], [%1], 16;" :: "r"(dst), "l"(src))
#define CP_ASYNC16_CA(dst, src) \
    asm volatile("cp.async.ca.shared.global [%0], [%1], 16;" :: "r"(dst), "l"(src))
#define CP_COMMIT() asm volatile("cp.async.commit_group;")
#define CP_WAIT1()  asm volatile("cp.async.wait_group 1;")
#define CP_WAIT0()  asm volatile("cp.async.wait_group 0;")

__device__ __forceinline__ uint32_t sw64(uint32_t off) {
    return off ^ ((off >> 3) & 0x30);
}

// ---------------- setup: twiddles + zero S/counters + Wcomb + bcomb ----------------
__global__ void setup_kernel(const float* __restrict__ Wo, const float* __restrict__ Wv,
                             const float* __restrict__ bv, const float* __restrict__ bo) {
    int blk = blockIdx.x;
    int tid = threadIdx.x;
    if (blk < 256) {
        __shared__ float As[32][33], Bs[32][33];
        int bi = (blk >> 4) * 32, bj = (blk & 15) * 32;
        int tx = tid & 15, ty = tid >> 4;
        float a00 = 0.f, a01 = 0.f, a10 = 0.f, a11 = 0.f;
        for (int m0 = 0; m0 < 512; m0 += 32) {
            for (int r = ty; r < 32; r += 16) {
                As[r][tx]      = Wo[(bi + r) * 512 + m0 + tx];
                As[r][tx + 16] = Wo[(bi + r) * 512 + m0 + tx + 16];
                Bs[r][tx]      = Wv[(m0 + r) * 512 + bj + tx];
                Bs[r][tx + 16] = Wv[(m0 + r) * 512 + bj + tx + 16];
            }
            __syncthreads();
#pragma unroll
            for (int m = 0; m < 32; ++m) {
                float x0 = As[ty][m], x1 = As[ty + 16][m];
                float y0 = Bs[m][tx], y1 = Bs[m][tx + 16];
                a00 += x0 * y0; a01 += x0 * y1; a10 += x1 * y0; a11 += x1 * y1;
            }
            __syncthreads();
        }
        int i00 = (bi + ty) * 512 + bj + tx;
        int i10 = (bi + ty + 16) * 512 + bj + tx;
        g_wcb[i00] = __float2half_rn(a00);      g_wcb[i00 + 16] = __float2half_rn(a01);
        g_wcb[i10] = __float2half_rn(a10);      g_wcb[i10 + 16] = __float2half_rn(a11);
    } else if (blk < 320) {
        int o = (blk - 256) * 8 + (tid >> 5);
        int lane = tid & 31;
        float s = 0.f;
        for (int m = lane; m < 512; m += 32) s += Wo[o * 512 + m] * bv[m];
#pragma unroll
        for (int off = 16; off; off >>= 1) s += __shfl_xor_sync(0xFFFFFFFFu, s, off);
        if (lane == 0) g_bcomb[o] = s + bo[o];
    } else if (blk == 320) {
        for (int j = tid; j < 2048; j += 256) {
            float s, c;
            sincospif(-2.0f * (float)j / (float)NFFT, &s, &c);
            g_tw[j] = make_float2(c, s);
        }
    } else {
        int i = (blk - 321) * 256 + tid;
        if (i < BB * 2049) g_S[i] = make_float2(0.f, 0.f);
        if (blk == 321 && tid < BB) g_cnt[tid] = 0;
    }
}

// ---------------- split: fp32 -> fp16 for xs, xw, Wq, Wk + conv relay ----------------
__device__ __forceinline__ void cvt_one4(const float4* __restrict__ x,
                                         __half2* __restrict__ f, int i) {
    float4 v = x[i];
    f[2 * i]     = __floats2half2_rn(v.x, v.y);
    f[2 * i + 1] = __floats2half2_rn(v.z, v.w);
}

__global__ void mega_split_kernel(const float4* __restrict__ xs,
                                  const float4* __restrict__ xw,
                                  const float4* __restrict__ Wq,
                                  const float4* __restrict__ Wk,
                                  const float* __restrict__ Wconv) {
    int bid = blockIdx.x;
    int tid = threadIdx.x;
    if (bid < 4096) {
        int base = bid * 1024 + tid;
#pragma unroll
        for (int j = 0; j < 4; ++j) cvt_one4(xs, (__half2*)g_xsf, base + j * 256);
    } else if (bid < 8192) {
        int base = (bid - 4096) * 1024 + tid;
#pragma unroll
        for (int j = 0; j < 4; ++j) cvt_one4(xw, (__half2*)g_xwf, base + j * 256);
    } else if (bid < 8448) {
        cvt_one4(Wq, (__half2*)g_wqf, (bid - 8192) * 256 + tid);
    } else if (bid < 8704) {
        cvt_one4(Wk, (__half2*)g_wkf, (bid - 8448) * 256 + tid);
    } else {
        int idx = (bid - 8704) * 256 + tid;         // conv relay; over 512*1536
        int n = idx / 1536;
        int r = idx - n * 1536;
        int kk = r >> 9;
        int i = r & 511;
        g_wc[idx] = __float2half_rn(Wconv[((size_t)n * 512 + i) * 3 + kk]);
    }
}

// ---------------- shared fp16 GEMM mainloop (3-stage ring, lookahead-2, 1 barrier/iter) ----------------
__device__ __forceinline__ void load_chunk16(
    int ch, int stage, int rowA, int rowB, bool conv, int m0, int n0, int tid, uint32_t sbase,
    const char* __restrict__ A, const char* __restrict__ B)
{
    uint32_t st = sbase + stage * 16384;
    int r = tid >> 1;
    int seg0 = (tid & 1) << 1;

    size_t abyte;
    if (conv) {
        int k0e = ch << 5;                 // element offset in logical K=1536 (fp16)
        int m = m0 + r;
        int kk = k0e >> 9;
        int ii = k0e & 511;
        int bb = m >> 12;
        int tt = ((m & 4095) + kk + 4095) & 4095;   // t + kk - 1 mod L
        abyte = ((((size_t)(bb << 12) + tt) << 9) + ii) * 2;
    } else {
        abyte = (size_t)(m0 + r) * rowA + (ch << 6);
    }
    size_t bbyte = (size_t)(n0 + r) * rowB + (ch << 6);

#pragma unroll
    for (int s2 = 0; s2 < 2; ++s2) {
        int seg = seg0 + s2;
        uint32_t soff = sw64((r << 6) + (seg << 4));
        CP_ASYNC16(st + soff, A + abyte + (seg << 4));
        CP_ASYNC16_CA(st + 8192 + soff, B + bbyte + (seg << 4));   // weights: L1-cached
    }
    CP_COMMIT();
}

__device__ __forceinline__ void gemm_mainloop(
    float acc[4][4][4], const char* __restrict__ A, const char* __restrict__ B,
    int rowA, int rowB, int T, bool conv, int m0, int n0, int tid, uint32_t sbase)
{
    const int wid = tid >> 5;
    const int lane = tid & 31;
    const int wm = wid >> 2;
    const int wn = wid & 3;
    const int lrow = lane & 15;
    const int lseg = lane >> 4;

#pragma unroll
    for (int i = 0; i < 4; ++i)
#pragma unroll
        for (int j = 0; j < 4; ++j)
#pragma unroll
            for (int r = 0; r < 4; ++r) acc[i][j][r] = 0.f;

    // lookahead-2 over a 3-stage ring: the load issued at iter 'it' targets stage
    // (it+2)%3 == (it-1)%3, whose reads were fenced by THIS iter's top barrier.
    load_chunk16(0, 0, rowA, rowB, conv, m0, n0, tid, sbase, A, B);
    load_chunk16(1, 1, rowA, rowB, conv, m0, n0, tid, sbase, A, B);

    int s = 0;
    for (int it = 0; it < T; ++it) {
        if (it + 1 < T) { CP_WAIT1(); } else { CP_WAIT0(); }
        __syncthreads();

        uint32_t st = sbase + s * 16384;
#pragma unroll
        for (int ks = 0; ks < 2; ++ks) {
            int cseg = (ks << 1) + lseg;
            uint32_t a[4][4], b2[2][4];
#pragma unroll
            for (int mt = 0; mt < 4; ++mt) {
                int row = (wm << 6) + (mt << 4) + lrow;
                ldmx4(a[mt], st + sw64((row << 6) + (cseg << 4)));
            }
#pragma unroll
            for (int bt = 0; bt < 2; ++bt) {
                int row = (wn << 5) + (bt << 4) + lrow;
                ldmx4(b2[bt], st + 8192 + sw64((row << 6) + (cseg << 4)));
            }
#pragma unroll
            for (int mt = 0; mt < 4; ++mt)
#pragma unroll
                for (int nt = 0; nt < 4; ++nt)
                    mma_f16(acc[mt][nt], a[mt],
                            b2[nt >> 1][nt & 1], b2[nt >> 1][(nt & 1) + 2]);
        }
        if (it + 2 < T) {
            int s2 = (s == 0) ? 2 : s - 1;     // (it+2)%3
            load_chunk16(it + 2, s2, rowA, rowB, conv, m0, n0, tid, sbase, A, B);
        }
        s = (s == 2) ? 0 : s + 1;
    }
    __syncthreads();    // protect smem reuse by epilogues
}

// ---------------- q/k GEMM (fp16, transposed fp16 output) ----------------
__global__ void __launch_bounds__(256, 2) qk_gemm(
    const float* __restrict__ bq, const float* __restrict__ bk)
{
    extern __shared__ char smraw[];
    uint32_t sbase = (smem_u32(smraw) + 1023u) & ~1023u;

    const int mode = blockIdx.x >> 10;     // 0 = q (x_w @ Wq), 1 = k (x_s @ Wk)
    const int rr = blockIdx.x & 1023;
    const int m0 = (rr >> 2) << 7;
    const int n0 = (rr & 3) << 7;
    const int tid = threadIdx.x;
    const int wid = tid >> 5;
    const int lane = tid & 31;
    const int wm = wid >> 2;
    const int wn = wid & 3;

    const char* A = (const char*)(mode ? g_xsf : g_xwf);
    const char* B = (const char*)(mode ? g_wkf : g_wqf);

    float acc[4][4][4];
    gemm_mainloop(acc, A, B, 1024, 1024, 16, false, m0, n0, tid, sbase);

    // fp16 transposed epilogue via smem into [B, D, L]
    const int er = lane >> 2;
    const int ec = (lane & 3) << 1;
    __half* sth = (__half*)smraw;
    const float* bias = mode ? bk : bq;
    __half* Cout = mode ? g_kTh : g_qTh;
#pragma unroll
    for (int mt = 0; mt < 4; ++mt)
#pragma unroll
        for (int nt = 0; nt < 4; ++nt) {
            int r0 = (wm << 6) + (mt << 4) + er;
            int c0 = (wn << 5) + (nt << 3) + ec;
            float b0v = bias[n0 + c0], b1v = bias[n0 + c0 + 1];
            sth[c0 * 136 + r0]            = __float2half_rn(acc[mt][nt][0] + b0v);
            sth[(c0 + 1) * 136 + r0]      = __float2half_rn(acc[mt][nt][1] + b1v);
            sth[c0 * 136 + r0 + 8]        = __float2half_rn(acc[mt][nt][2] + b0v);
            sth[(c0 + 1) * 136 + r0 + 8]  = __float2half_rn(acc[mt][nt][3] + b1v);
        }
    __syncthreads();
    int bb = m0 >> 12, l0 = m0 & 4095;
#pragma unroll
    for (int i = 0; i < 8; ++i) {
        int idx = tid + (i << 8);
        int c = idx >> 4;
        int g8 = (idx & 15) << 3;
        uint4 v = *(uint4*)&sth[c * 136 + g8];
        *(uint4*)&Cout[(((size_t)(bb << 9) + n0 + c) << 12) + l0 + g8] = v;
    }
}

// ---------------- fused radix-8 FFT (4 passes) ----------------
__device__ __forceinline__ float2 cmulf(float2 w, float2 z) {
    return make_float2(w.x * z.x - w.y * z.y, w.x * z.y + w.y * z.x);
}
__device__ __forceinline__ float2 mni(float2 u) { return make_float2(u.y, -u.x); }
__device__ __forceinline__ float2 rot45(float2 u) {
    const float r = 0.70710678118654752f;
    return make_float2(r * (u.x + u.y), r * (u.y - u.x));
}
__device__ __forceinline__ float2 cadd(float2 a, float2 b) { return make_float2(a.x + b.x, a.y + b.y); }
__device__ __forceinline__ float2 csub(float2 a, float2 b) { return make_float2(a.x - b.x, a.y - b.y); }

__device__ __forceinline__ void fft_stages_r8(float2* zs, const float2* tw, int tid) {
#pragma unroll
    for (int p = 0; p < 4; ++p) {
        const int h = 1 << (3 * p);
#pragma unroll
        for (int jj = 0; jj < 2; ++jj) {
            int j = tid + (jj << 8);
            int pos = j & (h - 1);
            int grp = j >> (3 * p);
            int base = (grp << (3 * p + 3)) + pos;
            float2 x0 = zs[base],         x1 = zs[base + h];
            float2 x2 = zs[base + 2 * h], x3 = zs[base + 3 * h];
            float2 x4 = zs[base + 4 * h], x5 = zs[base + 5 * h];
            float2 x6 = zs[base + 6 * h], x7 = zs[base + 7 * h];
            float2 wA = tw[pos << (11 - 3 * p)];
            float2 wB = tw[pos << (10 - 3 * p)];
            float2 wC = tw[pos << (9 - 3 * p)];
            float2 t;
            t = cmulf(wA, x1); float2 a0 = cadd(x0, t), a1 = csub(x0, t);
            t = cmulf(wA, x3); float2 a2 = cadd(x2, t), a3 = csub(x2, t);
            t = cmulf(wA, x5); float2 a4 = cadd(x4, t), a5 = csub(x4, t);
            t = cmulf(wA, x7); float2 a6 = cadd(x6, t), a7 = csub(x6, t);
            t = cmulf(wB, a2);      float2 b0 = cadd(a0, t), b2 = csub(a0, t);
            t = mni(cmulf(wB, a3)); float2 b1 = cadd(a1, t), b3 = csub(a1, t);
            t = cmulf(wB, a6);      float2 b4 = cadd(a4, t), b6 = csub(a4, t);
            t = mni(cmulf(wB, a7)); float2 b5 = cadd(a5, t), b7 = csub(a5, t);
            t = cmulf(wC, b4);             zs[base]         = cadd(b0, t); zs[base + 4 * h] = csub(b0, t);
            t = rot45(cmulf(wC, b5));      zs[base + h]     = cadd(b1, t); zs[base + 5 * h] = csub(b1, t);
            t = mni(cmulf(wC, b6));        zs[base + 2 * h] = cadd(b2, t); zs[base + 6 * h] = csub(b2, t);
            t = mni(rot45(cmulf(wC, b7))); zs[base + 3 * h] = cadd(b3, t); zs[base + 7 * h] = csub(b3, t);
        }
        __syncthreads();
    }
}

// ---------------- combo: fft_cross (512 CTAs, interleaved) + conv/P GEMM (2048 CTAs) ----------------
__global__ void __launch_bounds__(256, 2) combo_kernel(float* __restrict__ out_w)
{
    extern __shared__ char smraw[];
    const int bid = blockIdx.x;
    const int tid = threadIdx.x;

    if (bid < 2048 && (bid & 3) == 3) {
        // ---------------- fft_cross part ----------------
        float2* sm = (float2*)smraw;
        float2* zs  = sm;            // 4096
        float2* tw  = sm + 4096;     // 2048
        float2* acc = sm + 6144;     // 2049

        const int fidx = bid >> 2;
        const int b = fidx >> 6;
        const int dg = (fidx & 63) << 3;

        for (int j = tid; j < 2048; j += 256) tw[j] = g_tw[j];
        for (int f = tid; f <= 2048; f += 256) acc[f] = make_float2(0.f, 0.f);

        for (int c = 0; c < 8; ++c) {
            int d = dg + c;
            const __half2* qrow = (const __half2*)(g_qTh + (((size_t)b * DD + d) << 12));
            const __half2* krow = (const __half2*)(g_kTh + (((size_t)b * DD + d) << 12));
            __syncthreads();
#pragma unroll
            for (int k = 0; k < 8; ++k) {
                int idx = tid + (k << 8);
                float2 q2 = __half22float2(qrow[idx]);
                float2 k2 = __half22float2(krow[idx]);
                int t0 = idx << 1;
                zs[(int)(__brev((unsigned)t0) >> 20)]       = make_float2(q2.x, k2.x);
                zs[(int)(__brev((unsigned)(t0 + 1)) >> 20)] = make_float2(q2.y, k2.y);
            }
            __syncthreads();
            fft_stages_r8(zs, tw, tid);
            for (int f = tid; f <= 2048; f += 256) {
                float2 Zf = zs[f];
                float2 Zc = zs[(4096 - f) & 4095];
                float Qr = 0.5f * (Zf.x + Zc.x);
                float Qi = 0.5f * (Zf.y - Zc.y);
                float Kr = 0.5f * (Zf.y + Zc.y);
                float Ki = 0.5f * (Zc.x - Zf.x);
                float2 a2 = acc[f];
                a2.x += Qr * Kr + Qi * Ki;
                a2.y += Qi * Kr - Qr * Ki;
                acc[f] = a2;
            }
        }
        __syncthreads();
        for (int f = tid; f <= 2048; f += 256) {
            atomicAdd(&g_S[b * 2049 + f].x, acc[f].x);
            atomicAdd(&g_S[b * 2049 + f].y, acc[f].y);
        }

        // last-block: inline IFFT + top-k for this batch
        __shared__ int s_flag;
        __syncthreads();
        if (tid == 0) {
            __threadfence();
            int old = atomicAdd(&g_cnt[b], 1);
            s_flag = (old == 63) ? 1 : 0;
        }
        __syncthreads();
        if (!s_flag) return;
        __threadfence();

        float* mv = (float*)(sm + 6144);   // reuse acc region (4096 floats)

        for (int f = tid; f < 4096; f += 256) {
            float2 sv;
            if (f <= 2048) {
                sv = g_S[b * 2049 + f];
                sv.y = -sv.y;              // conj -> IFFT via forward FFT
            } else {
                sv = g_S[b * 2049 + (4096 - f)];
            }
            zs[(int)(__brev((unsigned)f) >> 20)] = sv;
        }
        __syncthreads();
        fft_stages_r8(zs, tw, tid);

        const float scale = 1.0f / (4096.0f * 512.0f);
        for (int n = tid; n < 4096; n += 256) mv[n] = zs[n].x * scale;
        __syncthreads();

        __shared__ float red_v[256];
        __shared__ int   red_i[256];
        __shared__ float s_tv[TOPK];
        __shared__ int   s_ti[TOPK];

        for (int it = 0; it < TOPK; ++it) {
            float bv = -3.402823e38f; int bi = 1 << 30;
            for (int n = tid; n < 4096; n += 256) {
                float v = mv[n];
                if (v > bv || (v == bv && n < bi)) { bv = v; bi = n; }
            }
            red_v[tid] = bv; red_i[tid] = bi;
            __syncthreads();
            for (int s = 128; s > 0; s >>= 1) {
                if (tid < s) {
                    float v2 = red_v[tid + s]; int i2 = red_i[tid + s];
                    if (v2 > red_v[tid] || (v2 == red_v[tid] && i2 < red_i[tid])) {
                        red_v[tid] = v2; red_i[tid] = i2;
                    }
                }
                __syncthreads();
            }
            if (tid == 0) {
                s_tv[it] = red_v[0]; s_ti[it] = red_i[0];
                mv[red_i[0]] = -3.402823e38f;
            }
            __syncthreads();
        }

        if (tid == 0) {
            float mx = s_tv[0];
            float ex[TOPK]; float sum = 0.f;
            for (int i = 0; i < TOPK; ++i) { ex[i] = expf(s_tv[i] - mx); sum += ex[i]; }
            for (int i = 0; i < TOPK; ++i) {
                g_w[b * TOPK + i] = ex[i] / sum;
                g_delay[b * TOPK + i] = s_ti[i];
            }
        }
        return;
    }

    // ---------------- GEMM part: conv (gidx < 1024) or P ----------------
    uint32_t sbase = (smem_u32(smraw) + 1023u) & ~1023u;
    int gidx = (bid < 2048) ? (bid - (bid >> 2)) : (1536 + (bid - 2048));
    const bool is_conv = (gidx < 1024);
    const int rr = gidx & 1023;
    const int m0 = (rr >> 2) << 7;
    const int n0 = (rr & 3) << 7;
    const int wid = tid >> 5;
    const int lane = tid & 31;
    const int wm = wid >> 2;
    const int wn = wid & 3;

    float acc[4][4][4];
    if (is_conv) {
        gemm_mainloop(acc, (const char*)g_xwf, (const char*)g_wc, 1024, 3072, 48, true,
                      m0, n0, tid, sbase);
    } else {
        gemm_mainloop(acc, (const char*)g_xsf, (const char*)g_wcb, 1024, 1024, 16, false,
                      m0, n0, tid, sbase);
    }

    const int er = lane >> 2;
    const int ec = (lane & 3) << 1;
    if (is_conv) {
#pragma unroll
        for (int mt = 0; mt < 4; ++mt)
#pragma unroll
            for (int nt = 0; nt < 4; ++nt) {
                int r0 = m0 + (wm << 6) + (mt << 4) + er;
                int c0 = n0 + (wn << 5) + (nt << 3) + ec;
                size_t o0 = ((size_t)r0 << 9) + c0;
                size_t o1 = ((size_t)(r0 + 8) << 9) + c0;
                *(float2*)&out_w[o0] = make_float2(acc[mt][nt][0], acc[mt][nt][1]);
                *(float2*)&out_w[o1] = make_float2(acc[mt][nt][2], acc[mt][nt][3]);
            }
    } else {
#pragma unroll
        for (int mt = 0; mt < 4; ++mt)
#pragma unroll
            for (int nt = 0; nt < 4; ++nt) {
                int r0 = m0 + (wm << 6) + (mt << 4) + er;
                int c0 = n0 + (wn << 5) + (nt << 3) + ec;
                *(__half2*)&g_P[((size_t)r0 << 9) + c0] =
                    __floats2half2_rn(acc[mt][nt][0], acc[mt][nt][1]);
                *(__half2*)&g_P[((size_t)(r0 + 8) << 9) + c0] =
                    __floats2half2_rn(acc[mt][nt][2], acc[mt][nt][3]);
            }
    }
}

// ---------------- final aggregation: out_s = x_s + sum_i w_i * roll(P, d_i) + bcomb ----------------
__global__ void final_agg(const float* __restrict__ xs, float* __restrict__ out) {
    size_t idx = (size_t)blockIdx.x * 256 + threadIdx.x;   // over B*L rows x 64 uint4-groups
    int c = (int)(idx & 63);
    size_t row = idx >> 6;
    int b = (int)(row >> 12);
    int t = (int)(row & 4095);

    float wloc[TOPK]; int dloc[TOPK];
#pragma unroll
    for (int i = 0; i < TOPK; ++i) { wloc[i] = g_w[b * TOPK + i]; dloc[i] = g_delay[b * TOPK + i]; }

    float acc[8];
    {
        const float4 b0 = *(const float4*)&g_bcomb[c << 3];
        const float4 b1 = *(const float4*)&g_bcomb[(c << 3) + 4];
        acc[0] = b0.x; acc[1] = b0.y; acc[2] = b0.z; acc[3] = b0.w;
        acc[4] = b1.x; acc[5] = b1.y; acc[6] = b1.z; acc[7] = b1.w;
    }
#pragma unroll
    for (int i = 0; i < TOPK; ++i) {
        int ts = (t + dloc[i]) & 4095;
        const uint4 raw = *(const uint4*)(g_P + (((size_t)(b << 12) + ts) << 9) + (c << 3));
        const __half2* p = (const __half2*)&raw;
        float w = wloc[i];
#pragma unroll
        for (int j = 0; j < 4; ++j) {
            float2 f = __half22float2(p[j]);
            acc[2 * j]     += w * f.x;
            acc[2 * j + 1] += w * f.y;
        }
    }
    size_t o = (row << 9) + (c << 3);
    const float4 xv0 = *(const float4*)&xs[o];
    const float4 xv1 = *(const float4*)&xs[o + 4];
    float4 r0 = make_float4(acc[0] + xv0.x, acc[1] + xv0.y, acc[2] + xv0.z, acc[3] + xv0.w);
    float4 r1 = make_float4(acc[4] + xv1.x, acc[5] + xv1.y, acc[6] + xv1.z, acc[7] + xv1.w);
    *(float4*)&out[o]     = r0;
    *(float4*)&out[o + 4] = r1;
}

// ---------------- host launch ----------------
extern "C" void kernel_launch(void* const* d_in, const int* in_sizes, int n_in,
                              void* d_out, int out_size) {
    const float* x_s   = (const float*)d_in[0];
    const float* x_w   = (const float*)d_in[1];
    const float* Wq    = (const float*)d_in[2];
    const float* bq    = (const float*)d_in[3];
    const float* Wk    = (const float*)d_in[4];
    const float* bk    = (const float*)d_in[5];
    const float* Wv    = (const float*)d_in[6];
    const float* bv    = (const float*)d_in[7];
    const float* Wo    = (const float*)d_in[8];
    const float* bo    = (const float*)d_in[9];
    const float* Wconv = (const float*)d_in[10];

    float* out_s = (float*)d_out;
    float* out_w = out_s + BLD;

    const int SMEM_GEMM = 3 * 16384 + 1024;      // 50176
    const int SMEM_COMBO = 66560;                // fft path needs (4096+2048+2049)*8
    cudaFuncSetAttribute(qk_gemm, cudaFuncAttributeMaxDynamicSharedMemorySize, SMEM_GEMM);
    cudaFuncSetAttribute(combo_kernel, cudaFuncAttributeMaxDynamicSharedMemorySize, SMEM_COMBO);

    // 1: twiddles + zero spectrum/counters + Wcomb + bcomb
    setup_kernel<<<386, 256>>>(Wo, Wv, bv, bo);
    // 2: fp16 conversions + conv weight relay
    mega_split_kernel<<<11776, 256>>>((const float4*)x_s, (const float4*)x_w,
                                      (const float4*)Wq, (const float4*)Wk, Wconv);
    // 3: q and k projections (transposed fp16 outputs)
    qk_gemm<<<2048, 256, SMEM_GEMM>>>(bq, bk);
    // 4: fft_cross interleaved with conv + P GEMMs; last fft CTA per batch does IFFT+top-k
    combo_kernel<<<2560, 256, SMEM_COMBO>>>(out_w);
    // 5: out_s = x_s + sum_i w_i * roll(P, d_i) + bcomb
    final_agg<<<8192, 256>>>(x_s, out_s);
}